// round 10
// baseline (speedup 1.0000x reference)
#include <cuda_runtime.h>
#include <math.h>

// Problem constants
#define NB    4
#define NC    17
#define NH    128
#define NW    128
#define HWSZ  (NH*NW)
#define NPC   51
#define NWID  128
#define NSTEP 48
#define ALIVE_IDX 3
#define ALIVE_THR 0.1f

#define CHW   (NC*HWSZ)
#define BCHW  (NB*CHW)
#define FINAL_ELEMS (NB*4*HWSZ)
#define NBLK  256

typedef unsigned long long ull;

// f32x2 packed-pair helpers
#define F2FMA(d, a, b, c) asm("fma.rn.f32x2 %0, %1, %2, %3;" : "=l"(d) : "l"(a), "l"(b), "l"(c))
#define F2MUL2(d, a, b)   asm("mul.rn.f32x2 %0, %1, %2;"     : "=l"(d) : "l"(a), "l"(b))
#define F2ADD(d, a, b)    asm("add.rn.f32x2 %0, %1, %2;"     : "=l"(d) : "l"(a), "l"(b))
#define PK2(d, lo, hi)    asm("mov.b64 %0, {%1, %2};" : "=l"(d) : "f"(lo), "f"(hi))
#define UPK2(lo, hi, s)   asm("mov.b64 {%0, %1}, %2;" : "=f"(lo), "=f"(hi) : "l"(s))

// Static device scratch
__device__ float         g_alive[NB * HWSZ];   // unmasked new alive channel
__device__ unsigned char g_ssum[NB * 256];     // per-strip "any alive pixel" summary
__device__ unsigned      g_count;
__device__ volatile unsigned g_sense;

// Flat sense-reversal barrier, HOT SPIN (no nanosleep).
__device__ __forceinline__ void grid_barrier(unsigned target) {
    __syncthreads();
    if (threadIdx.x == 0) {
        __threadfence();
        if (atomicAdd(&g_count, 1u) == NBLK - 1u) {
            g_count = 0u;
            __threadfence();
            g_sense = target;
        } else {
            while (g_sense != target) { }
            __threadfence();
        }
    }
    __syncthreads();
}

// Dynamic smem layout (ull units)
#define S_W1  0                      // 128 rows x 52 dup W1
#define S_W2  (S_W1 + 128*52)        // 128 rows x 18 dup W2^T
#define S_B1  (S_W2 + 128*18)        // 128 dup b1
#define S_B2  (S_B1 + 128)           // 18 dup b2
#define S_PB  (S_B2 + 20)            // 32 pairs x 54 p-vector buffer
#define PBS   54
#define SMEM_ULLS (S_PB + 32*PBS)
#define SMEM_BYTES (SMEM_ULLS * 8)

__global__ __launch_bounds__(128, 2)
void nca_persistent(const float* __restrict__ init_state,
                    const float* __restrict__ rnd_all,
                    const float* __restrict__ W1, const float* __restrict__ b1,
                    const float* __restrict__ W2, const float* __restrict__ b2,
                    float* __restrict__ dev_path,   // [48,B,C,H,W] (pre-zeroed)
                    float* __restrict__ final_out)  // [B,4,H,W]   (pre-zeroed)
{
    extern __shared__ ull smem[];
    __shared__ int sActive[4];
    const int tid = threadIdx.x;

    // ---- load duplicated weights once ----
    for (int i = tid; i < 128 * 52; i += 128) {
        int o = i / 52, c = i - o * 52;
        float wv = (c < NPC) ? W1[o * NPC + c] : 0.0f;
        ull d; PK2(d, wv, wv); smem[S_W1 + i] = d;
    }
    for (int i = tid; i < 128 * 18; i += 128) {
        int o = i / 18, j = i - o * 18;
        float wv = (j < NC) ? W2[j * NWID + o] : 0.0f;
        ull d; PK2(d, wv, wv); smem[S_W2 + i] = d;
    }
    { float wv = b1[tid]; ull d; PK2(d, wv, wv); smem[S_B1 + tid] = d; }
    if (tid < 18) { float wv = (tid < NC) ? b2[tid] : 0.0f; ull d; PK2(d, wv, wv); smem[S_B2 + tid] = d; }

    int bias_ok = (b1[tid] <= 0.0f);
    if (tid < NC) bias_ok = bias_ok && (b2[tid] == 0.0f);
    const int allz = __syncthreads_and(bias_ok);

    // ---- geometry (R7): block = (batch, 16x16 tile); warp w = 16x4 strip ----
    const int bid = blockIdx.x;
    const int b   = bid >> 6;
    const int tle = bid & 63;
    const int bx0 = (tle & 7) * 16;
    const int by0 = (tle >> 3) * 16;

    const int w    = tid >> 5;           // warp = own strip 0..3
    const int lane = tid & 31;

    // owner-pixel mapping (phase B + transition clears): 16x16 tile
    const int opr = tid & 7, oly = tid >> 3;
    const int ox0 = bx0 + opr * 2, oy = by0 + oly;
    const int opix = oy * NW + ox0;

    // strip grid coords (8 cols x 32 rows per batch)
    const int srx = tle & 7;
    const int sry = (tle >> 3) * 4 + w;
    const int sy0 = by0 + 4 * w;

    // cooperative mapping for A2: pair 0..31, quad 0..3
    const int mpair = tid >> 2, mq = tid & 3;
    const int mpr = mpair & 7, mply = mpair >> 3;

    unsigned bsense = 0;
    bool wasActive = true;
    const float* cur = init_state;

    #pragma unroll 1
    for (int t = 0; t < NSTEP; t++) {
        float* dst = dev_path + (size_t)t * BCHW;

        // ========== PHASE A1: skip check ==========
        bool nowActive = true;
        if (allz) {
            if (t == 0) {
                // exact t=0 check: any init alive value > thr in strip+2px halo (20x8)
                float v = 0.0f;
                const float* ia = init_state + (b * NC + ALIVE_IDX) * HWSZ;
                #pragma unroll
                for (int k = 0; k < 5; k++) {
                    int i = lane + 32 * k;
                    int cx = bx0 - 2 + (i % 20);
                    int cy = sy0 - 2 + (i / 20);
                    if (i < 160 && cx >= 0 && cx < NW && cy >= 0 && cy < NH)
                        v = fmaxf(v, __ldg(ia + cy * NW + cx));
                }
                nowActive = __any_sync(0xFFFFFFFFu, v > ALIVE_THR);
                if (!nowActive) {
                    // stale-replay cleanup: zero g_alive + summary once
                    *reinterpret_cast<ull*>(&g_alive[b * HWSZ + opix]) = 0ULL;
                    if (lane == 0) g_ssum[b * 256 + sry * 8 + srx] = 0;
                }
            } else {
                // 3x3 strip-summary check (9 bytes)
                unsigned char f = 0;
                if (lane < 9) {
                    int nry = sry + (lane / 3) - 1;
                    int nrx = srx + (lane % 3) - 1;
                    if (nry >= 0 && nry < 32 && nrx >= 0 && nrx < 8)
                        f = __ldcg(&g_ssum[b * 256 + nry * 8 + nrx]);
                }
                nowActive = __any_sync(0xFFFFFFFFu, f != 0);
                if (!nowActive && wasActive)
                    *reinterpret_cast<ull*>(&g_alive[b * HWSZ + opix]) = 0ULL;
            }
        }
        wasActive = nowActive;
        if (lane == 0) sActive[w] = nowActive ? 1 : 0;
        __syncthreads();

        // ========== PHASE A2: cooperative compute of active own strips ==========
        #pragma unroll 1
        for (int s = 0; s < 4; s++) {
            if (!sActive[s]) continue;

            const int mx0  = bx0 + mpr * 2;
            const int my   = by0 + s * 4 + mply;
            const int mpix = my * NW + mx0;
            ull* pb = smem + S_PB + mpair * PBS;

            // --- cooperative conv: 4 threads/pair, channels mq,mq+4,... ---
            {
                const int xm1 = (mx0 >= 1) ? mx0 - 1 : 0;
                const int xp2 = (mx0 + 2 < NW) ? mx0 + 2 : NW - 1;
                const int ym1 = (my >= 1) ? my - 1 : 0;
                const int yp1 = (my + 1 < NH) ? my + 1 : NH - 1;
                const int oy0 = ym1 * NW, oy1 = my * NW, oy2 = yp1 * NW;
                const float fy0 = (my >= 1) ? 1.0f : 0.0f;
                const float fy2 = (my + 1 < NH) ? 1.0f : 0.0f;
                const float fx0 = (mx0 >= 1) ? 1.0f : 0.0f;
                const float fx3 = (mx0 + 2 < NW) ? 1.0f : 0.0f;
                const float m00 = fy0 * fx0, m03 = fy0 * fx3;
                const float m20 = fy2 * fx0, m23 = fy2 * fx3;

                for (int c = mq; c < NC; c += 4) {
                    const float* ch = cur + (b * NC + c) * HWSZ;
                    float a00 = __ldg(ch + oy0 + xm1) * m00;
                    float a01 = __ldg(ch + oy0 + mx0) * fy0;
                    float a02 = __ldg(ch + oy0 + mx0 + 1) * fy0;
                    float a03 = __ldg(ch + oy0 + xp2) * m03;
                    float a10 = __ldg(ch + oy1 + xm1) * fx0;
                    float a11 = __ldg(ch + oy1 + mx0);
                    float a12 = __ldg(ch + oy1 + mx0 + 1);
                    float a13 = __ldg(ch + oy1 + xp2) * fx3;
                    float a20 = __ldg(ch + oy2 + xm1) * m20;
                    float a21 = __ldg(ch + oy2 + mx0) * fy2;
                    float a22 = __ldg(ch + oy2 + mx0 + 1) * fy2;
                    float a23 = __ldg(ch + oy2 + xp2) * m23;

                    float gxA = ((a02 - a00) + 2.0f * (a12 - a10) + (a22 - a20)) * 0.125f;
                    float gxB = ((a03 - a01) + 2.0f * (a13 - a11) + (a23 - a21)) * 0.125f;
                    float gyA = ((a20 - a00) + 2.0f * (a21 - a01) + (a22 - a02)) * 0.125f;
                    float gyB = ((a21 - a01) + 2.0f * (a22 - a02) + (a23 - a03)) * 0.125f;

                    ull d;
                    PK2(d, a11, a12); pb[c] = d;
                    PK2(d, gxA, gxB); pb[17 + c] = d;
                    PK2(d, gyA, gyB); pb[34 + c] = d;

                    if (c == 16) {
                        float saA, caA, saB, caB;
                        sincosf(a11, &saA, &caA);
                        sincosf(a12, &saB, &caB);
                        ull ca2, sa2;
                        PK2(ca2, caA, caB); PK2(sa2, saA, saB);
                        pb[51] = 0ULL; pb[52] = ca2; pb[53] = sa2;
                    }
                }
            }
            __syncthreads();

            // --- cooperative MLP: thread (pair, quad), o = 4*i + quad ---
            {
                ull p2[52];
                const ulonglong2* pbr = reinterpret_cast<const ulonglong2*>(pb);
                #pragma unroll
                for (int q = 0; q < 26; q++) {
                    ulonglong2 v = pbr[q];
                    p2[2 * q] = v.x; p2[2 * q + 1] = v.y;
                }
                {
                    ull ca2 = pb[52], sa2 = pb[53];
                    float sA, sB; UPK2(sA, sB, sa2);
                    ull nsa2; PK2(nsa2, -sA, -sB);
                    #pragma unroll
                    for (int c = 0; c < NC; c++) {
                        ull gx2 = p2[17 + c], gy2 = p2[34 + c], u;
                        F2MUL2(u, ca2, gx2); F2FMA(u, sa2, gy2, u);  p2[17 + c] = u;
                        F2MUL2(u, ca2, gy2); F2FMA(u, nsa2, gx2, u); p2[34 + c] = u;
                    }
                }

                ull dx2[18];
                #pragma unroll
                for (int j = 0; j < 18; j++)
                    dx2[j] = (mq == 0) ? smem[S_B2 + j] : 0ULL;

                #pragma unroll 1
                for (int i = 0; i < 32; i++) {
                    const int o = 4 * i + mq;
                    ull acc0 = smem[S_B1 + o];
                    ull acc1 = 0ULL, acc2 = 0ULL, acc3 = 0ULL;
                    const ulonglong2* r = reinterpret_cast<const ulonglong2*>(smem + S_W1 + o * 52);
                    #pragma unroll
                    for (int q = 0; q < 13; q++) {
                        ulonglong2 wv = r[q];
                        ulonglong2 wu = r[q + 13];
                        F2FMA(acc0, wv.x, p2[2 * q],      acc0);
                        F2FMA(acc1, wv.y, p2[2 * q + 1],  acc1);
                        F2FMA(acc2, wu.x, p2[2 * q + 26], acc2);
                        F2FMA(acc3, wu.y, p2[2 * q + 27], acc3);
                    }
                    ull s02, s13, hs;
                    F2ADD(s02, acc0, acc2); F2ADD(s13, acc1, acc3); F2ADD(hs, s02, s13);
                    float hA, hB; UPK2(hA, hB, hs);
                    hA = fmaxf(hA, 0.0f); hB = fmaxf(hB, 0.0f);
                    ull h2; PK2(h2, hA, hB);

                    const ulonglong2* r2 = reinterpret_cast<const ulonglong2*>(smem + S_W2 + o * 18);
                    #pragma unroll
                    for (int q = 0; q < 9; q++) {
                        ulonglong2 wv = r2[q];
                        F2FMA(dx2[2 * q],     wv.x, h2, dx2[2 * q]);
                        F2FMA(dx2[2 * q + 1], wv.y, h2, dx2[2 * q + 1]);
                    }
                }

                #pragma unroll
                for (int j = 0; j < 18; j++) {
                    ull o2 = __shfl_down_sync(0xFFFFFFFFu, dx2[j], 2, 4);
                    F2ADD(dx2[j], dx2[j], o2);
                    o2 = __shfl_down_sync(0xFFFFFFFFu, dx2[j], 1, 4);
                    F2ADD(dx2[j], dx2[j], o2);
                }

                if (mq == 0) {
                    const float2 rr = *reinterpret_cast<const float2*>(
                        rnd_all + ((size_t)t * NB + b) * HWSZ + mpix);
                    float mA = (rr.x < 0.5f) ? 1.0f : 0.0f;
                    float mB = (rr.y < 0.5f) ? 1.0f : 0.0f;
                    ull m2; PK2(m2, mA, mB);
                    float* dout = dst + b * CHW + mpix;
                    #pragma unroll
                    for (int c = 0; c < NC; c++) {
                        ull nv; F2FMA(nv, dx2[c], m2, p2[c]);
                        *reinterpret_cast<ull*>(dout + c * HWSZ) = nv;
                        if (c == ALIVE_IDX)
                            *reinterpret_cast<ull*>(&g_alive[b * HWSZ + mpix]) = nv;
                    }
                }
            }
            __syncthreads();
        }

        bsense ^= 1u; grid_barrier(bsense);

        // ========== PHASE B: alive masking + summary write (own strip) ==========
        const bool last = (t == NSTEP - 1);
        if (sActive[w]) {
            float* dout = dst + b * CHW + opix;
            float mo[4] = {-1e30f, -1e30f, -1e30f, -1e30f};
            float mn[4] = {-1e30f, -1e30f, -1e30f, -1e30f};
            const float* oa = cur + (b * NC + ALIVE_IDX) * HWSZ;
            const unsigned naoff = b * HWSZ;
            #pragma unroll
            for (int dy = -1; dy <= 1; dy++) {
                int yy = oy + dy;
                if (yy < 0 || yy >= NH) continue;
                #pragma unroll
                for (int dxx = -1; dxx <= 2; dxx++) {
                    int xx = ox0 + dxx;
                    if (xx < 0 || xx >= NW) continue;
                    int idx = yy * NW + xx;
                    float ov = __ldg(oa + idx);
                    float nv = __ldcg(&g_alive[naoff + idx]);
                    mo[dxx + 1] = fmaxf(mo[dxx + 1], ov);
                    mn[dxx + 1] = fmaxf(mn[dxx + 1], nv);
                }
            }
            float moA = fmaxf(fmaxf(mo[0], mo[1]), mo[2]);
            float moB = fmaxf(fmaxf(mo[1], mo[2]), mo[3]);
            float mnA = fmaxf(fmaxf(mn[0], mn[1]), mn[2]);
            float mnB = fmaxf(fmaxf(mn[1], mn[2]), mn[3]);
            const bool aliveA = (moA > ALIVE_THR) && (mnA > ALIVE_THR);
            const bool aliveB = (moB > ALIVE_THR) && (mnB > ALIVE_THR);

            if (!aliveA && !aliveB) {
                #pragma unroll
                for (int c = 0; c < NC; c++)
                    *reinterpret_cast<ull*>(dout + c * HWSZ) = 0ULL;
            } else if (!aliveA) {
                #pragma unroll
                for (int c = 0; c < NC; c++) dout[c * HWSZ] = 0.0f;
            } else if (!aliveB) {
                #pragma unroll
                for (int c = 0; c < NC; c++) dout[c * HWSZ + 1] = 0.0f;
            }

            // strip summary: any alive pixel in this strip?
            const bool warpAlive = __any_sync(0xFFFFFFFFu, aliveA || aliveB);
            if (lane == 0)
                g_ssum[b * 256 + sry * 8 + srx] = warpAlive ? 1 : 0;

            if (last && (aliveA || aliveB)) {
                #pragma unroll
                for (int c = 0; c < 4; c++) {
                    float vA = aliveA ? dout[c * HWSZ]     : 0.0f;
                    float vB = aliveB ? dout[c * HWSZ + 1] : 0.0f;
                    float2 fv; fv.x = vA; fv.y = vB;
                    *reinterpret_cast<float2*>(final_out + (b * 4 + c) * HWSZ + opix) = fv;
                }
            }
        }

        bsense ^= 1u; grid_barrier(bsense);
        cur = dst;
    }
}

// ---------------------------------------------------------------------------
// Inputs: 0 init_state [4,17,128,128], 1 rand [48,4,1,128,128],
//         2 W1 [128,51], 3 b1 [128], 4 W2 [17,128], 5 b2 [17]
// Output f32: final[:, :4] (262144) then dev_path (48*4*17*128*128).
// ---------------------------------------------------------------------------
extern "C" void kernel_launch(void* const* d_in, const int* in_sizes, int n_in,
                              void* d_out, int out_size)
{
    const float* init_state = (const float*)d_in[0];
    const float* rnd        = (const float*)d_in[1];
    const float* W1         = (const float*)d_in[2];
    const float* b1         = (const float*)d_in[3];
    const float* W2         = (const float*)d_in[4];
    const float* b2         = (const float*)d_in[5];

    float* out      = (float*)d_out;
    float* final_p  = out;
    float* dev_path = out + FINAL_ELEMS;

    cudaMemsetAsync(d_out, 0, (size_t)out_size * sizeof(float));

    cudaFuncSetAttribute(nca_persistent,
                         cudaFuncAttributeMaxDynamicSharedMemorySize, SMEM_BYTES);

    nca_persistent<<<NBLK, 128, SMEM_BYTES>>>(init_state, rnd, W1, b1, W2, b2,
                                              dev_path, final_p);
}

// round 11
// speedup vs baseline: 1.4390x; 1.4390x over previous
#include <cuda_runtime.h>
#include <math.h>

// Problem constants
#define NB    4
#define NC    17
#define NH    128
#define NW    128
#define HWSZ  (NH*NW)
#define NPC   51
#define NWID  128
#define NSTEP 48
#define ALIVE_IDX 3
#define ALIVE_THR 0.1f

#define CHW   (NC*HWSZ)
#define BCHW  (NB*CHW)
#define FINAL_ELEMS (NB*4*HWSZ)
#define NBLK  256
#define NSTRIP 1024
#define QCAP  2048
#define ZF    0x8000

typedef unsigned long long ull;

// f32x2 packed-pair helpers
#define F2FMA(d, a, b, c) asm("fma.rn.f32x2 %0, %1, %2, %3;" : "=l"(d) : "l"(a), "l"(b), "l"(c))
#define F2MUL2(d, a, b)   asm("mul.rn.f32x2 %0, %1, %2;"     : "=l"(d) : "l"(a), "l"(b))
#define F2ADD(d, a, b)    asm("add.rn.f32x2 %0, %1, %2;"     : "=l"(d) : "l"(a), "l"(b))
#define PK2(d, lo, hi)    asm("mov.b64 %0, {%1, %2};" : "=l"(d) : "f"(lo), "f"(hi))
#define UPK2(lo, hi, s)   asm("mov.b64 {%0, %1}, %2;" : "=f"(lo), "=f"(hi) : "l"(s))

// Static device scratch
__device__ float    g_alive[NB * HWSZ];   // unmasked new alive channel
__device__ int      g_claim[NSTRIP];      // per-strip claim epoch
__device__ int      g_q[2][QCAP];         // double-buffered strip queue
__device__ unsigned g_qn[2];              // queue counts
__device__ unsigned g_count;
__device__ volatile unsigned g_sense;

// R7 barrier verbatim (nanosleep spin — proven).
__device__ __forceinline__ void grid_barrier(unsigned target) {
    __syncthreads();
    if (threadIdx.x == 0) {
        __threadfence();
        if (atomicAdd(&g_count, 1u) == NBLK - 1u) {
            g_count = 0u;
            __threadfence();
            g_sense = target;
        } else {
            while (g_sense != target) __nanosleep(32);
            __threadfence();
        }
    }
    __syncthreads();
}

// Dynamic smem layout (ull units)
#define S_W1  0
#define S_W2  (S_W1 + 128*52)
#define S_B1  (S_W2 + 128*18)
#define S_B2  (S_B1 + 128)
#define S_PB  (S_B2 + 20)
#define PBS   54
#define SMEM_ULLS (S_PB + 32*PBS)
#define SMEM_BYTES (SMEM_ULLS * 8)

__global__ __launch_bounds__(128, 2)
void nca_persistent(const float* __restrict__ init_state,
                    const float* __restrict__ rnd_all,
                    const float* __restrict__ W1, const float* __restrict__ b1,
                    const float* __restrict__ W2, const float* __restrict__ b2,
                    float* __restrict__ dev_path,   // [48,B,C,H,W] (pre-zeroed)
                    float* __restrict__ final_out)  // [B,4,H,W]   (pre-zeroed)
{
    extern __shared__ ull smem[];
    const int tid = threadIdx.x;

    // ---- load duplicated weights once (R7 verbatim) ----
    for (int i = tid; i < 128 * 52; i += 128) {
        int o = i / 52, c = i - o * 52;
        float wv = (c < NPC) ? W1[o * NPC + c] : 0.0f;
        ull d; PK2(d, wv, wv); smem[S_W1 + i] = d;
    }
    for (int i = tid; i < 128 * 18; i += 128) {
        int o = i / 18, j = i - o * 18;
        float wv = (j < NC) ? W2[j * NWID + o] : 0.0f;
        ull d; PK2(d, wv, wv); smem[S_W2 + i] = d;
    }
    { float wv = b1[tid]; ull d; PK2(d, wv, wv); smem[S_B1 + tid] = d; }
    if (tid < 18) { float wv = (tid < NC) ? b2[tid] : 0.0f; ull d; PK2(d, wv, wv); smem[S_B2 + tid] = d; }

    int bias_ok = (b1[tid] <= 0.0f);
    if (tid < NC) bias_ok = bias_ok && (b2[tid] == 0.0f);
    const int allz = __syncthreads_and(bias_ok);

    const int bid  = blockIdx.x;
    const int lane = tid & 31;

    // cooperative mapping: pair 0..31, quad 0..3
    const int mpair = tid >> 2, mq = tid & 3;
    const int mpr = mpair & 7, mply = mpair >> 3;

    // replay safety: clear own claims (visible to B(0) claims via barrier1(0))
    if (tid < 4) g_claim[bid * 4 + tid] = 0;

    unsigned bsense = 0;
    const float* cur = init_state;

    #pragma unroll 1
    for (int t = 0; t < NSTEP; t++) {
        float* dst = dev_path + (size_t)t * BCHW;
        const int par = (t + 1) & 1;     // queue slot written this step

        // reset the slot B(t) will append to (consumed two regions ago)
        if (bid == 0 && tid == 0) g_qn[par] = 0;

        const bool dense = (t == 0) || (!allz);
        const unsigned nq = dense ? NSTRIP : __ldcg(&g_qn[t & 1]);

        // ================= PHASE A: compute queued strips =================
        #pragma unroll 1
        for (unsigned k = (unsigned)bid; k < nq; k += NBLK) {
            const int e = dense ? (int)k : __ldcg(&g_q[t & 1][k]);
            if (e & ZF) {
                // zero-only entry: clear stale g_alive unless strip is computed this step
                const int s = e & (ZF - 1);
                if (__ldcg(&g_claim[s]) != t) {
                    const int zb   = s >> 8;
                    const int ztle = (s >> 2) & 63;
                    const int zx0  = (ztle & 7) * 16;
                    const int zy0  = (ztle >> 3) * 16 + (s & 3) * 4;
                    if (tid < 64)
                        g_alive[zb * HWSZ + (zy0 + (tid >> 4)) * NW + zx0 + (tid & 15)] = 0.0f;
                }
                continue;
            }
            // decode strip
            const int sb   = e >> 8;
            const int tle  = (e >> 2) & 63;
            const int sbx0 = (tle & 7) * 16;
            const int syb  = (tle >> 3) * 16 + (e & 3) * 4;

            const int mx0  = sbx0 + mpr * 2;
            const int my   = syb + mply;
            const int mpix = my * NW + mx0;
            ull* pb = smem + S_PB + mpair * PBS;

            // --- cooperative conv (R7 verbatim) ---
            {
                const int xm1 = (mx0 >= 1) ? mx0 - 1 : 0;
                const int xp2 = (mx0 + 2 < NW) ? mx0 + 2 : NW - 1;
                const int ym1 = (my >= 1) ? my - 1 : 0;
                const int yp1 = (my + 1 < NH) ? my + 1 : NH - 1;
                const int oy0 = ym1 * NW, oy1 = my * NW, oy2 = yp1 * NW;
                const float fy0 = (my >= 1) ? 1.0f : 0.0f;
                const float fy2 = (my + 1 < NH) ? 1.0f : 0.0f;
                const float fx0 = (mx0 >= 1) ? 1.0f : 0.0f;
                const float fx3 = (mx0 + 2 < NW) ? 1.0f : 0.0f;
                const float m00 = fy0 * fx0, m03 = fy0 * fx3;
                const float m20 = fy2 * fx0, m23 = fy2 * fx3;

                for (int c = mq; c < NC; c += 4) {
                    const float* ch = cur + (sb * NC + c) * HWSZ;
                    float a00 = __ldg(ch + oy0 + xm1) * m00;
                    float a01 = __ldg(ch + oy0 + mx0) * fy0;
                    float a02 = __ldg(ch + oy0 + mx0 + 1) * fy0;
                    float a03 = __ldg(ch + oy0 + xp2) * m03;
                    float a10 = __ldg(ch + oy1 + xm1) * fx0;
                    float a11 = __ldg(ch + oy1 + mx0);
                    float a12 = __ldg(ch + oy1 + mx0 + 1);
                    float a13 = __ldg(ch + oy1 + xp2) * fx3;
                    float a20 = __ldg(ch + oy2 + xm1) * m20;
                    float a21 = __ldg(ch + oy2 + mx0) * fy2;
                    float a22 = __ldg(ch + oy2 + mx0 + 1) * fy2;
                    float a23 = __ldg(ch + oy2 + xp2) * m23;

                    float gxA = ((a02 - a00) + 2.0f * (a12 - a10) + (a22 - a20)) * 0.125f;
                    float gxB = ((a03 - a01) + 2.0f * (a13 - a11) + (a23 - a21)) * 0.125f;
                    float gyA = ((a20 - a00) + 2.0f * (a21 - a01) + (a22 - a02)) * 0.125f;
                    float gyB = ((a21 - a01) + 2.0f * (a22 - a02) + (a23 - a03)) * 0.125f;

                    ull d;
                    PK2(d, a11, a12); pb[c] = d;
                    PK2(d, gxA, gxB); pb[17 + c] = d;
                    PK2(d, gyA, gyB); pb[34 + c] = d;

                    if (c == 16) {
                        float saA, caA, saB, caB;
                        sincosf(a11, &saA, &caA);
                        sincosf(a12, &saB, &caB);
                        ull ca2, sa2;
                        PK2(ca2, caA, caB); PK2(sa2, saA, saB);
                        pb[51] = 0ULL; pb[52] = ca2; pb[53] = sa2;
                    }
                }
            }
            __syncthreads();

            // --- cooperative MLP (R7 verbatim) ---
            {
                ull p2[52];
                const ulonglong2* pbr = reinterpret_cast<const ulonglong2*>(pb);
                #pragma unroll
                for (int q = 0; q < 26; q++) {
                    ulonglong2 v = pbr[q];
                    p2[2 * q] = v.x; p2[2 * q + 1] = v.y;
                }
                {
                    ull ca2 = pb[52], sa2 = pb[53];
                    float sA, sB; UPK2(sA, sB, sa2);
                    ull nsa2; PK2(nsa2, -sA, -sB);
                    #pragma unroll
                    for (int c = 0; c < NC; c++) {
                        ull gx2 = p2[17 + c], gy2 = p2[34 + c], u;
                        F2MUL2(u, ca2, gx2); F2FMA(u, sa2, gy2, u);  p2[17 + c] = u;
                        F2MUL2(u, ca2, gy2); F2FMA(u, nsa2, gx2, u); p2[34 + c] = u;
                    }
                }

                ull dx2[18];
                #pragma unroll
                for (int j = 0; j < 18; j++)
                    dx2[j] = (mq == 0) ? smem[S_B2 + j] : 0ULL;

                #pragma unroll 1
                for (int i = 0; i < 32; i++) {
                    const int o = 4 * i + mq;
                    ull acc0 = smem[S_B1 + o];
                    ull acc1 = 0ULL, acc2 = 0ULL, acc3 = 0ULL;
                    const ulonglong2* r = reinterpret_cast<const ulonglong2*>(smem + S_W1 + o * 52);
                    #pragma unroll
                    for (int q = 0; q < 13; q++) {
                        ulonglong2 wv = r[q];
                        ulonglong2 wu = r[q + 13];
                        F2FMA(acc0, wv.x, p2[2 * q],      acc0);
                        F2FMA(acc1, wv.y, p2[2 * q + 1],  acc1);
                        F2FMA(acc2, wu.x, p2[2 * q + 26], acc2);
                        F2FMA(acc3, wu.y, p2[2 * q + 27], acc3);
                    }
                    ull s02, s13, hs;
                    F2ADD(s02, acc0, acc2); F2ADD(s13, acc1, acc3); F2ADD(hs, s02, s13);
                    float hA, hB; UPK2(hA, hB, hs);
                    hA = fmaxf(hA, 0.0f); hB = fmaxf(hB, 0.0f);
                    ull h2; PK2(h2, hA, hB);

                    const ulonglong2* r2 = reinterpret_cast<const ulonglong2*>(smem + S_W2 + o * 18);
                    #pragma unroll
                    for (int q = 0; q < 9; q++) {
                        ulonglong2 wv = r2[q];
                        F2FMA(dx2[2 * q],     wv.x, h2, dx2[2 * q]);
                        F2FMA(dx2[2 * q + 1], wv.y, h2, dx2[2 * q + 1]);
                    }
                }

                #pragma unroll
                for (int j = 0; j < 18; j++) {
                    ull o2 = __shfl_down_sync(0xFFFFFFFFu, dx2[j], 2, 4);
                    F2ADD(dx2[j], dx2[j], o2);
                    o2 = __shfl_down_sync(0xFFFFFFFFu, dx2[j], 1, 4);
                    F2ADD(dx2[j], dx2[j], o2);
                }

                if (mq == 0) {
                    const float2 rr = *reinterpret_cast<const float2*>(
                        rnd_all + ((size_t)t * NB + sb) * HWSZ + mpix);
                    float mA = (rr.x < 0.5f) ? 1.0f : 0.0f;
                    float mB = (rr.y < 0.5f) ? 1.0f : 0.0f;
                    ull m2; PK2(m2, mA, mB);
                    float* dout = dst + sb * CHW + mpix;
                    #pragma unroll
                    for (int c = 0; c < NC; c++) {
                        ull nv; F2FMA(nv, dx2[c], m2, p2[c]);
                        *reinterpret_cast<ull*>(dout + c * HWSZ) = nv;
                        if (c == ALIVE_IDX)
                            *reinterpret_cast<ull*>(&g_alive[sb * HWSZ + mpix]) = nv;
                    }
                }
            }
            __syncthreads();
        }

        bsense ^= 1u; grid_barrier(bsense);

        // ================= PHASE B: mask + enqueue next step =================
        const bool last = (t == NSTEP - 1);
        #pragma unroll 1
        for (unsigned k = (unsigned)bid; k < nq; k += NBLK) {
            const int e = dense ? (int)k : __ldcg(&g_q[t & 1][k]);
            if (e & ZF) continue;
            const int sb   = e >> 8;
            const int tle  = (e >> 2) & 63;
            const int scol = (e >> 2) & 7;
            const int srow = ((e >> 5) & 7) * 4 + (e & 3);
            const int sbx0 = (tle & 7) * 16;
            const int syb  = (tle >> 3) * 16 + (e & 3) * 4;

            bool aliveA = false, aliveB = false;
            if (tid < 32) {
                const int px0 = sbx0 + (tid & 7) * 2;
                const int py  = syb + (tid >> 3);
                float* dout = dst + sb * CHW + py * NW + px0;

                float mo[4] = {-1e30f, -1e30f, -1e30f, -1e30f};
                float mn[4] = {-1e30f, -1e30f, -1e30f, -1e30f};
                const float* oa = cur + (sb * NC + ALIVE_IDX) * HWSZ;
                const unsigned naoff = sb * HWSZ;
                #pragma unroll
                for (int dy = -1; dy <= 1; dy++) {
                    int yy = py + dy;
                    if (yy < 0 || yy >= NH) continue;
                    #pragma unroll
                    for (int dxx = -1; dxx <= 2; dxx++) {
                        int xx = px0 + dxx;
                        if (xx < 0 || xx >= NW) continue;
                        int idx = yy * NW + xx;
                        float ov = __ldg(oa + idx);
                        float nv = __ldcg(&g_alive[naoff + idx]);
                        mo[dxx + 1] = fmaxf(mo[dxx + 1], ov);
                        mn[dxx + 1] = fmaxf(mn[dxx + 1], nv);
                    }
                }
                float moA = fmaxf(fmaxf(mo[0], mo[1]), mo[2]);
                float moB = fmaxf(fmaxf(mo[1], mo[2]), mo[3]);
                float mnA = fmaxf(fmaxf(mn[0], mn[1]), mn[2]);
                float mnB = fmaxf(fmaxf(mn[1], mn[2]), mn[3]);
                aliveA = (moA > ALIVE_THR) && (mnA > ALIVE_THR);
                aliveB = (moB > ALIVE_THR) && (mnB > ALIVE_THR);

                if (!aliveA && !aliveB) {
                    #pragma unroll
                    for (int c = 0; c < NC; c++)
                        *reinterpret_cast<ull*>(dout + c * HWSZ) = 0ULL;
                } else if (!aliveA) {
                    #pragma unroll
                    for (int c = 0; c < NC; c++) dout[c * HWSZ] = 0.0f;
                } else if (!aliveB) {
                    #pragma unroll
                    for (int c = 0; c < NC; c++) dout[c * HWSZ + 1] = 0.0f;
                }

                if (last && (aliveA || aliveB)) {
                    #pragma unroll
                    for (int c = 0; c < 4; c++) {
                        float vA = aliveA ? dout[c * HWSZ]     : 0.0f;
                        float vB = aliveB ? dout[c * HWSZ + 1] : 0.0f;
                        float2 fv; fv.x = vA; fv.y = vB;
                        *reinterpret_cast<float2*>(final_out + (sb * 4 + c) * HWSZ + py * NW + px0) = fv;
                    }
                }

                // enqueue for step t+1 (warp0 only; full-warp sync ops)
                if (!last && allz) {
                    const bool any = __any_sync(0xFFFFFFFFu, aliveA || aliveB);
                    if (any) {
                        if (lane < 9) {
                            int nr  = srow + (lane / 3) - 1;
                            int ncl = scol + (lane % 3) - 1;
                            if (nr >= 0 && nr < 32 && ncl >= 0 && ncl < 8) {
                                int ns = (sb * 64 + (nr >> 2) * 8 + ncl) * 4 + (nr & 3);
                                int old = atomicExch(&g_claim[ns], t + 1);
                                if (old != t + 1) {
                                    unsigned idx = atomicAdd(&g_qn[par], 1u);
                                    g_q[par][idx] = ns;
                                }
                            }
                        }
                    } else if (lane == 0) {
                        if (__ldcg(&g_claim[e]) != t + 1) {
                            unsigned idx = atomicAdd(&g_qn[par], 1u);
                            g_q[par][idx] = e | ZF;
                        }
                    }
                }
            }
        }

        bsense ^= 1u; grid_barrier(bsense);
        cur = dst;
    }
}

// ---------------------------------------------------------------------------
// Inputs: 0 init_state [4,17,128,128], 1 rand [48,4,1,128,128],
//         2 W1 [128,51], 3 b1 [128], 4 W2 [17,128], 5 b2 [17]
// Output f32: final[:, :4] (262144) then dev_path (48*4*17*128*128).
// ---------------------------------------------------------------------------
extern "C" void kernel_launch(void* const* d_in, const int* in_sizes, int n_in,
                              void* d_out, int out_size)
{
    const float* init_state = (const float*)d_in[0];
    const float* rnd        = (const float*)d_in[1];
    const float* W1         = (const float*)d_in[2];
    const float* b1         = (const float*)d_in[3];
    const float* W2         = (const float*)d_in[4];
    const float* b2         = (const float*)d_in[5];

    float* out      = (float*)d_out;
    float* final_p  = out;
    float* dev_path = out + FINAL_ELEMS;

    cudaMemsetAsync(d_out, 0, (size_t)out_size * sizeof(float));

    cudaFuncSetAttribute(nca_persistent,
                         cudaFuncAttributeMaxDynamicSharedMemorySize, SMEM_BYTES);

    nca_persistent<<<NBLK, 128, SMEM_BYTES>>>(init_state, rnd, W1, b1, W2, b2,
                                              dev_path, final_p);
}